// round 11
// baseline (speedup 1.0000x reference)
#include <cuda_runtime.h>
#include <cuda_bf16.h>
#include <cstdint>
#include <cfloat>
#include <math.h>

#define Bsz 1024
#define Qsz 65536
#define Dsz 512
#define MARGINf 0.4f
#define SCALEf 32.0f
#define K2f 46.166241308446828f   /* 32*log2(e) */
#define NT2 512                   /* q-tiles of 128 slots (q0 GEMM) */
#define MT2 64                    /* masked-compact tiles of 128 */
#define MCAP 8192
#define CPAD 133

// ---------------- static device scratch (no allocations) ----------------
__device__ __align__(16) __nv_bfloat16 g_qbf[(size_t)Qsz * Dsz];     // q0 bf16, 64 MB
__device__ __align__(16) __nv_bfloat16 g_pbf[Bsz * Dsz];             // 1 MB
__device__ __align__(16) __nv_bfloat16 g_qm[(size_t)MCAP * Dsz];     // masked q1 rows, 8 MB
__device__ int   g_midx[MCAP];
__device__ int   g_mcount;
__device__ float g_s1 [(size_t)NT2 * Bsz];
__device__ float g_s1m[(size_t)NT2 * Bsz];
__device__ float g_s2b[(size_t)MT2 * Bsz];
__device__ float g_t1 [(size_t)NT2 * 256 * 10];
__device__ float g_t1u[(size_t)NT2 * 256 * 10];
__device__ float g_t2b[(size_t)MT2 * 256 * 10];
__device__ float g_row[Bsz];

// ---------------- helpers ----------------
__device__ __forceinline__ float ex2f(float x) {
    float y;
    asm("ex2.approx.ftz.f32 %0, %1;" : "=f"(y) : "f"(x));
    return y;
}

__device__ __forceinline__ void ins10(float (&t)[10], float v) {
    if (v <= t[9]) return;
    #pragma unroll
    for (int i = 0; i < 10; ++i) {
        float a  = t[i];
        float hi = fmaxf(a, v);
        float lo = fminf(a, v);
        t[i] = hi;
        v    = lo;
    }
}

#define MMA16816(ac, Ar, b0, b1)                                                        \
    asm volatile(                                                                       \
        "mma.sync.aligned.m16n8k16.row.col.f32.bf16.bf16.f32 "                          \
        "{%0,%1,%2,%3},{%4,%5,%6,%7},{%8,%9},{%0,%1,%2,%3};"                            \
        : "+f"(ac[0]), "+f"(ac[1]), "+f"(ac[2]), "+f"(ac[3])                            \
        : "r"(Ar[0]), "r"(Ar[1]), "r"(Ar[2]), "r"(Ar[3]), "r"(b0), "r"(b1))

// =====================================================================
// Pass 0a: fp32 -> bf16 staging for p and queue[0]
// =====================================================================
__global__ void k_convert(const float* __restrict__ p, const float* __restrict__ q) {
    int i = blockIdx.x * blockDim.x + threadIdx.x;
    const int PN4 = (Bsz * Dsz) / 4;
    const int TOT = PN4 + (Qsz * Dsz) / 4;
    if (i >= TOT) return;
    float4 v;
    __nv_bfloat162* dst;
    if (i < PN4) {
        v   = ((const float4*)p)[i];
        dst = (__nv_bfloat162*)g_pbf + (size_t)i * 2;
    } else {
        size_t j = (size_t)i - PN4;
        v   = ((const float4*)q)[j];
        dst = (__nv_bfloat162*)g_qbf + j * 2;
    }
    dst[0] = __floats2bfloat162_rn(v.x, v.y);
    dst[1] = __floats2bfloat162_rn(v.z, v.w);
}

// =====================================================================
// Pass 0b: compact masked slot indices — coalesced strided access.
// =====================================================================
__global__ void __launch_bounds__(1024) k_scan(const float* __restrict__ maskp) {
    __shared__ int cnt[1024];
    int t = threadIdx.x;
    int local = 0;
    #pragma unroll 4
    for (int i = 0; i < 64; ++i) local += (maskp[i * 1024 + t] != 0.f);
    cnt[t] = local;
    __syncthreads();
    for (int o = 1; o < 1024; o <<= 1) {
        int v = (t >= o) ? cnt[t - o] : 0;
        __syncthreads();
        cnt[t] += v;
        __syncthreads();
    }
    if (t == 1023) g_mcount = cnt[1023] < MCAP ? cnt[1023] : MCAP;
    int j = cnt[t] - local;
    for (int i = 0; i < 64; ++i) {
        int idx = i * 1024 + t;
        if (maskp[idx] != 0.f) {
            if (j < MCAP) g_midx[j] = idx;
            ++j;
        }
    }
}

// =====================================================================
// Pass 0c: gather+convert masked q1 rows (zero-fill beyond count)
// =====================================================================
__global__ void __launch_bounds__(128) k_gather(const float* __restrict__ q) {
    int j = blockIdx.x, t = threadIdx.x;
    int count = g_mcount;
    __nv_bfloat162* dst = (__nv_bfloat162*)(g_qm + (size_t)j * Dsz);
    if (j < count) {
        const float4* src =
            (const float4*)(q + (size_t)Qsz * Dsz + (size_t)g_midx[j] * Dsz);
        float4 v = src[t];
        dst[t * 2]     = __floats2bfloat162_rn(v.x, v.y);
        dst[t * 2 + 1] = __floats2bfloat162_rn(v.z, v.w);
    } else {
        __nv_bfloat162 z = __floats2bfloat162_rn(0.f, 0.f);
        dst[t * 2]     = z;
        dst[t * 2 + 1] = z;
    }
}

// =====================================================================
// Merged Pass 1 + 1b: bf16 GEMM (128x128xK512) + fused epilogue.
// grid (8 b-tiles [fast], 512 q0-tiles + 64 masked tiles), 256 threads.
// 2-stage cp.async pipeline; __launch_bounds__(256,3) caps regs at 85 so
// 3 CTAs/SM fit (regs 65280<=65536, smem 3x74240=222720<=228KB).
// smem: [0,512) mask[128]; [512,+73728) 2 x 36864B stages (reused as Csh).
// =====================================================================
__global__ void __launch_bounds__(256, 3) k_mm(const float* __restrict__ maskp,
                                               const int* __restrict__ label) {
    extern __shared__ char sm_[];
    float* maskSh = (float*)sm_;
    char*  buf    = sm_ + 512;
    const int RS  = 144;
    const int ASZ = 128 * RS;     // 18432
    const int STG = 2 * ASZ;      // 36864 per stage

    int tid = threadIdx.x, lane = tid & 31, w = tid >> 5;
    int wm = w & 3, wn = w >> 2;
    int bx = blockIdx.x, by = blockIdx.y;
    bool isB = (by >= NT2);
    int count = g_mcount;
    int jb = isB ? (by - NT2) * 128 : 0;

    if (isB && jb >= count) {                 // dead masked tile
        if (bx == 0) {
            int byb = by - NT2;
            for (int r = tid; r < Bsz; r += 256) g_s2b[(size_t)byb * Bsz + r] = 0.f;
            for (int i = tid; i < 2560; i += 256) g_t2b[(size_t)byb * 2560 + i] = -FLT_MAX;
        }
        return;
    }

    const __nv_bfloat16* gp = g_pbf + (size_t)bx * 128 * Dsz;
    const __nv_bfloat16* gq = isB ? (g_qm + (size_t)jb * Dsz)
                                  : (g_qbf + (size_t)by * 128 * Dsz);
    if (!isB && tid < 128) maskSh[tid] = maskp[by * 128 + tid];

    uint32_t sbase = (uint32_t)__cvta_generic_to_shared(buf);

    // closed-form copy offsets: i = tid + 256t -> c = tid&7 (const), r = (tid>>3)+32t
    const uint32_t off0 = (uint32_t)((tid >> 3) * RS + (tid & 7) * 16);      // +4608*t
    const uint32_t gof0 = (uint32_t)((tid >> 3) * 1024 + (tid & 7) * 16);    // +32768*t

    float acc[2][8][4];
    #pragma unroll
    for (int mt = 0; mt < 2; ++mt)
        #pragma unroll
        for (int nt = 0; nt < 8; ++nt)
            #pragma unroll
            for (int j = 0; j < 4; ++j) acc[mt][nt][j] = 0.f;

    auto issue = [&](int ks, int s) {
        uint32_t ab = sbase + s * STG + off0;
        uint32_t bb = ab + ASZ;
        const char* gA = (const char*)gp + ks * 128 + gof0;
        const char* gB = (const char*)gq + ks * 128 + gof0;
        #pragma unroll
        for (int t = 0; t < 4; ++t) {
            asm volatile("cp.async.cg.shared.global [%0],[%1],16;"
                         :: "r"(ab + t * 4608u), "l"(gA + t * 32768));
            asm volatile("cp.async.cg.shared.global [%0],[%1],16;"
                         :: "r"(bb + t * 4608u), "l"(gB + t * 32768));
        }
        asm volatile("cp.async.commit_group;");
    };

    auto compute = [&](int s) {
        uint32_t ab = sbase + s * STG;
        uint32_t bb = ab + ASZ;
        uint32_t aBase = ab + (wm * 32 + (lane & 15)) * RS + (lane >> 4) * 16;
        int bq = lane >> 3;
        uint32_t bPart = bb + (wn * 64 + (bq >> 1) * 8 + (lane & 7)) * RS + (bq & 1) * 16;
        #pragma unroll
        for (int kk = 0; kk < 4; ++kk) {
            uint32_t A[2][4];
            #pragma unroll
            for (int mt = 0; mt < 2; ++mt) {
                uint32_t ad = aBase + mt * 16 * RS + kk * 32;
                asm volatile("ldmatrix.sync.aligned.m8n8.x4.shared.b16 {%0,%1,%2,%3},[%4];"
                             : "=r"(A[mt][0]), "=r"(A[mt][1]), "=r"(A[mt][2]), "=r"(A[mt][3])
                             : "r"(ad));
            }
            #pragma unroll
            for (int np = 0; np < 4; ++np) {
                uint32_t bd = bPart + np * 16 * RS + kk * 32;
                uint32_t B0, B1, B2, B3;
                asm volatile("ldmatrix.sync.aligned.m8n8.x4.shared.b16 {%0,%1,%2,%3},[%4];"
                             : "=r"(B0), "=r"(B1), "=r"(B2), "=r"(B3) : "r"(bd));
                #pragma unroll
                for (int mt = 0; mt < 2; ++mt) {
                    MMA16816(acc[mt][2 * np],     A[mt], B0, B1);
                    MMA16816(acc[mt][2 * np + 1], A[mt], B2, B3);
                }
            }
        }
    };

    issue(0, 0);
    #pragma unroll 1
    for (int ks = 0; ks < 8; ++ks) {
        if (ks < 7) {
            issue(ks + 1, (ks + 1) & 1);
            asm volatile("cp.async.wait_group 1;");
        } else {
            asm volatile("cp.async.wait_group 0;");
        }
        __syncthreads();
        compute(ks & 1);
        __syncthreads();
    }

    // ---- C tile -> smem (68096 B <= 73728 B stage region) ----
    float* Csh = (float*)buf;
    #pragma unroll
    for (int mt = 0; mt < 2; ++mt)
        #pragma unroll
        for (int nt = 0; nt < 8; ++nt) {
            int r = wm * 32 + mt * 16 + (lane >> 2);
            int c = wn * 64 + nt * 8 + 2 * (lane & 3);
            Csh[r * CPAD + c]           = acc[mt][nt][0];
            Csh[r * CPAD + c + 1]       = acc[mt][nt][1];
            Csh[(r + 8) * CPAD + c]     = acc[mt][nt][2];
            Csh[(r + 8) * CPAD + c + 1] = acc[mt][nt][3];
        }
    __syncthreads();

    if (!isB) {
        // tid<128 : s1 (all cols) + top10 all; tid>=128 : s1m (masked) + top10 unmasked
        int  r     = tid & 127;
        bool roleB = (tid >= 128);
        int  gb    = bx * 128 + r;
        bool neg   = (label[gb] == -1);

        float s = 0.f;
        float top[10];
        #pragma unroll
        for (int i = 0; i < 10; ++i) top[i] = -FLT_MAX;

        const float* Crow = Csh + r * CPAD;
        for (int c = 0; c < 128; ++c) {
            float v = Crow[c];
            bool  mskd = (maskSh[c] != 0.f);
            if (!roleB) {
                s += ex2f(K2f * v);
                if (neg) ins10(top, v);
            } else {
                if (mskd) s += ex2f(K2f * v);
                else if (neg) ins10(top, v);
            }
        }

        size_t si = (size_t)by * Bsz + gb;
        if (!roleB) g_s1[si] = s; else g_s1m[si] = s;
        if (neg) {
            size_t ti = ((size_t)by * 256 + (gb >> 2)) * 10;
            float* gt_ = roleB ? g_t1u : g_t1;
            #pragma unroll
            for (int i = 0; i < 10; ++i) gt_[ti + i] = top[i];
        }
    } else if (tid < 128) {
        int  byb = by - NT2;
        int  r   = tid;
        int  gb  = bx * 128 + r;
        bool neg = (label[gb] == -1);
        int  nvalid = count - jb; if (nvalid > 128) nvalid = 128;

        float s = 0.f;
        float top[10];
        #pragma unroll
        for (int i = 0; i < 10; ++i) top[i] = -FLT_MAX;

        const float* Crow = Csh + r * CPAD;
        for (int c = 0; c < nvalid; ++c) {
            float v = Crow[c];
            s += ex2f(K2f * v);
            if (neg) ins10(top, v);
        }
        g_s2b[(size_t)byb * Bsz + gb] = s;
        if (neg) {
            size_t ti = ((size_t)byb * 256 + (gb >> 2)) * 10;
            #pragma unroll
            for (int i = 0; i < 10; ++i) g_t2b[ti + i] = top[i];
        }
    }
}

// =====================================================================
// Pass 2: per-row merge
// =====================================================================
__global__ void __launch_bounds__(256) k_pass2(const float* __restrict__ p,
                                               const float* __restrict__ q,
                                               const float* __restrict__ maskp,
                                               const int* __restrict__ label) {
    __shared__ float red[256];
    __shared__ float red2[256];
    __shared__ float red3[256];
    __shared__ float cand[2560];
    __shared__ float wv_[8];
    __shared__ int   wi_[8];

    int b = blockIdx.x, tid = threadIdx.x;
    int lab = label[b];

    if (lab != -1) {
        float s1 = 0.f, s1m = 0.f, s2b = 0.f;
        for (int t = tid; t < NT2; t += 256) {
            s1  += g_s1 [(size_t)t * Bsz + b];
            s1m += g_s1m[(size_t)t * Bsz + b];
            if (t < MT2) s2b += g_s2b[(size_t)t * Bsz + b];
        }
        red[tid] = s1; red2[tid] = s1m; red3[tid] = s2b;
        __syncthreads();
        for (int o = 128; o > 0; o >>= 1) {
            if (tid < o) {
                red[tid]  += red[tid + o];
                red2[tid] += red2[tid + o];
                red3[tid] += red3[tid + o];
            }
            __syncthreads();
        }
        float S1 = red[0];
        float S2 = red[0] - red2[0] + red3[0];
        __syncthreads();

        float d1 = 0.f, d2 = 0.f;
        float mk = maskp[lab];
        const float* pr = p + (size_t)b * Dsz;
        const float* q0 = q + (size_t)lab * Dsz;
        const float* q1 = q0 + (size_t)Qsz * Dsz;
        for (int d = tid; d < Dsz; d += 256) {
            float pv = pr[d], a0 = q0[d], a1 = q1[d];
            float wv = mk * a1 + (1.f - mk) * a0;
            d1 += pv * a0;
            d2 += pv * wv;
        }
        red[tid] = d1; red2[tid] = d2;
        __syncthreads();
        for (int o = 128; o > 0; o >>= 1) {
            if (tid < o) { red[tid] += red[tid + o]; red2[tid] += red2[tid + o]; }
            __syncthreads();
        }
        if (tid == 0) {
            float gt1 = red[0], gt2 = red2[0];
            float sp1 = S1 - ex2f(K2f * gt1) + ex2f(K2f * (gt1 - MARGINf));
            float sp2 = S2 - ex2f(K2f * gt2) + ex2f(K2f * (gt2 - MARGINf));
            float ce1 = logf(sp1) - (gt1 - MARGINf) * SCALEf;
            float ce2 = logf(sp2) - (gt2 - MARGINf) * SCALEf;
            g_row[b] = ce1 + ce2;
        }
    } else {
        float negsum = 0.f;
        size_t base = (size_t)(b >> 2) * 10;
        for (int mat = 0; mat < 2; ++mat) {
            float top[10];
            #pragma unroll
            for (int i = 0; i < 10; ++i) top[i] = -FLT_MAX;
            int nlists = (mat == 0) ? NT2 : (NT2 + MT2);
            for (int t = tid; t < nlists; t += 256) {
                const float* L;
                if (mat == 0)        L = g_t1  + (size_t)t * 2560 + base;
                else if (t < NT2)    L = g_t1u + (size_t)t * 2560 + base;
                else                 L = g_t2b + (size_t)(t - NT2) * 2560 + base;
                #pragma unroll
                for (int i = 0; i < 10; ++i) {
                    float v = L[i];
                    if (v <= top[9]) break;   // lists sorted descending
                    ins10(top, v);
                }
            }
            #pragma unroll
            for (int i = 0; i < 10; ++i) cand[tid * 10 + i] = top[i];
            __syncthreads();

            for (int it = 0; it < 10; ++it) {
                float bv = -FLT_MAX; int bi = -1;
                #pragma unroll
                for (int j = 0; j < 10; ++j) {
                    float v = cand[tid * 10 + j];
                    if (v > bv) { bv = v; bi = tid * 10 + j; }
                }
                #pragma unroll
                for (int o = 16; o > 0; o >>= 1) {
                    float ov = __shfl_down_sync(0xffffffffu, bv, o);
                    int   oi = __shfl_down_sync(0xffffffffu, bi, o);
                    if (ov > bv) { bv = ov; bi = oi; }
                }
                if ((tid & 31) == 0) { wv_[tid >> 5] = bv; wi_[tid >> 5] = bi; }
                __syncthreads();
                if (tid == 0) {
                    float mv = wv_[0]; int mi = wi_[0];
                    #pragma unroll
                    for (int k = 1; k < 8; ++k)
                        if (wv_[k] > mv) { mv = wv_[k]; mi = wi_[k]; }
                    cand[mi] = -FLT_MAX;
                    negsum += fmaxf(mv, 0.f);
                }
                __syncthreads();
            }
            __syncthreads();
        }
        if (tid == 0) g_row[b] = negsum * 0.1f;
    }
}

// =====================================================================
// Pass 3: scalar reduction
// =====================================================================
__global__ void k_final(const int* __restrict__ label, float* __restrict__ out) {
    __shared__ float sp[256], sn[256];
    __shared__ int   cp_[256], cn_[256];
    int tid = threadIdx.x;
    float ps = 0.f, ns = 0.f;
    int pc = 0, nc = 0;
    for (int b = tid; b < Bsz; b += 256) {
        if (label[b] != -1) { ps += g_row[b]; pc++; }
        else                { ns += g_row[b]; nc++; }
    }
    sp[tid] = ps; sn[tid] = ns; cp_[tid] = pc; cn_[tid] = nc;
    __syncthreads();
    for (int o = 128; o > 0; o >>= 1) {
        if (tid < o) {
            sp[tid] += sp[tid + o]; sn[tid] += sn[tid + o];
            cp_[tid] += cp_[tid + o]; cn_[tid] += cn_[tid + o];
        }
        __syncthreads();
    }
    if (tid == 0) {
        float r = 0.f;
        if (cp_[0] > 0) r += sp[0] / (float)cp_[0];
        if (cn_[0] > 0) r += sn[0] / (float)cn_[0];
        out[0] = r;
    }
}

// =====================================================================
extern "C" void kernel_launch(void* const* d_in, const int* in_sizes, int n_in,
                              void* d_out, int out_size) {
    const float* p   = (const float*)d_in[0];
    const float* q   = (const float*)d_in[1];
    const float* mk  = (const float*)d_in[2];
    const int*   lab = (const int*)d_in[3];
    float* out = (float*)d_out;

    const int SMEM1 = 512 + 2 * 36864;   // 74240
    cudaFuncSetAttribute(k_mm, cudaFuncAttributeMaxDynamicSharedMemorySize, SMEM1);

    k_convert<<<33280, 256>>>(p, q);
    k_scan<<<1, 1024>>>(mk);
    k_gather<<<MCAP, 128>>>(q);
    dim3 g1(8, NT2 + MT2);
    k_mm<<<g1, 256, SMEM1>>>(mk, lab);
    k_pass2<<<Bsz, 256>>>(p, q, mk, lab);
    k_final<<<1, 256>>>(lab, out);
}

// round 12
// speedup vs baseline: 1.1703x; 1.1703x over previous
#include <cuda_runtime.h>
#include <cuda_bf16.h>
#include <cstdint>
#include <cfloat>
#include <math.h>

#define Bsz 1024
#define Qsz 65536
#define Dsz 512
#define MARGINf 0.4f
#define SCALEf 32.0f
#define K2f 46.166241308446828f   /* 32*log2(e) */
#define NT2 512                   /* q-tiles of 128 slots (q0 GEMM) */
#define MT2 64                    /* masked-compact tiles of 128 */
#define MCAP 8192
#define CPAD 133

// ---------------- static device scratch (no allocations) ----------------
__device__ __align__(16) __nv_bfloat16 g_qbf[(size_t)Qsz * Dsz];     // q0 bf16, 64 MB
__device__ __align__(16) __nv_bfloat16 g_pbf[Bsz * Dsz];             // 1 MB
__device__ __align__(16) __nv_bfloat16 g_qm[(size_t)MCAP * Dsz];     // masked q1 rows, 8 MB
__device__ int   g_midx[MCAP];
__device__ int   g_mcount;
__device__ float g_s1 [(size_t)NT2 * Bsz];
__device__ float g_s1m[(size_t)NT2 * Bsz];
__device__ float g_s2b[(size_t)MT2 * Bsz];
__device__ float g_t1 [(size_t)NT2 * 256 * 10];
__device__ float g_t1u[(size_t)NT2 * 256 * 10];
__device__ float g_t2b[(size_t)MT2 * 256 * 10];
__device__ float g_row[Bsz];

// ---------------- helpers ----------------
__device__ __forceinline__ float ex2f(float x) {
    float y;
    asm("ex2.approx.ftz.f32 %0, %1;" : "=f"(y) : "f"(x));
    return y;
}

__device__ __forceinline__ void ins10(float (&t)[10], float v) {
    if (v <= t[9]) return;
    #pragma unroll
    for (int i = 0; i < 10; ++i) {
        float a  = t[i];
        float hi = fmaxf(a, v);
        float lo = fminf(a, v);
        t[i] = hi;
        v    = lo;
    }
}

#define MMA16816(ac, Ar, b0, b1)                                                        \
    asm volatile(                                                                       \
        "mma.sync.aligned.m16n8k16.row.col.f32.bf16.bf16.f32 "                          \
        "{%0,%1,%2,%3},{%4,%5,%6,%7},{%8,%9},{%0,%1,%2,%3};"                            \
        : "+f"(ac[0]), "+f"(ac[1]), "+f"(ac[2]), "+f"(ac[3])                            \
        : "r"(Ar[0]), "r"(Ar[1]), "r"(Ar[2]), "r"(Ar[3]), "r"(b0), "r"(b1))

// =====================================================================
// Pass 0a: fp32 -> bf16 staging for p and queue[0]
// =====================================================================
__global__ void k_convert(const float* __restrict__ p, const float* __restrict__ q) {
    int i = blockIdx.x * blockDim.x + threadIdx.x;
    const int PN4 = (Bsz * Dsz) / 4;
    const int TOT = PN4 + (Qsz * Dsz) / 4;
    if (i >= TOT) return;
    float4 v;
    __nv_bfloat162* dst;
    if (i < PN4) {
        v   = ((const float4*)p)[i];
        dst = (__nv_bfloat162*)g_pbf + (size_t)i * 2;
    } else {
        size_t j = (size_t)i - PN4;
        v   = ((const float4*)q)[j];
        dst = (__nv_bfloat162*)g_qbf + j * 2;
    }
    dst[0] = __floats2bfloat162_rn(v.x, v.y);
    dst[1] = __floats2bfloat162_rn(v.z, v.w);
}

// =====================================================================
// Pass 0b: compact masked slot indices — coalesced strided access.
// =====================================================================
__global__ void __launch_bounds__(1024) k_scan(const float* __restrict__ maskp) {
    __shared__ int cnt[1024];
    int t = threadIdx.x;
    int local = 0;
    #pragma unroll 4
    for (int i = 0; i < 64; ++i) local += (maskp[i * 1024 + t] != 0.f);
    cnt[t] = local;
    __syncthreads();
    for (int o = 1; o < 1024; o <<= 1) {
        int v = (t >= o) ? cnt[t - o] : 0;
        __syncthreads();
        cnt[t] += v;
        __syncthreads();
    }
    if (t == 1023) g_mcount = cnt[1023] < MCAP ? cnt[1023] : MCAP;
    int j = cnt[t] - local;
    for (int i = 0; i < 64; ++i) {
        int idx = i * 1024 + t;
        if (maskp[idx] != 0.f) {
            if (j < MCAP) g_midx[j] = idx;
            ++j;
        }
    }
}

// =====================================================================
// Pass 0c: gather+convert masked q1 rows (zero-fill beyond count)
// =====================================================================
__global__ void __launch_bounds__(128) k_gather(const float* __restrict__ q) {
    int j = blockIdx.x, t = threadIdx.x;
    int count = g_mcount;
    __nv_bfloat162* dst = (__nv_bfloat162*)(g_qm + (size_t)j * Dsz);
    if (j < count) {
        const float4* src =
            (const float4*)(q + (size_t)Qsz * Dsz + (size_t)g_midx[j] * Dsz);
        float4 v = src[t];
        dst[t * 2]     = __floats2bfloat162_rn(v.x, v.y);
        dst[t * 2 + 1] = __floats2bfloat162_rn(v.z, v.w);
    } else {
        __nv_bfloat162 z = __floats2bfloat162_rn(0.f, 0.f);
        dst[t * 2]     = z;
        dst[t * 2 + 1] = z;
    }
}

// =====================================================================
// Merged Pass 1 + 1b: bf16 GEMM (128x128xK512) + fused epilogue.
// grid (8 b-tiles [fast], 512 q0-tiles + 64 masked tiles), 512 threads.
// 16 warps in a 4x4 grid, each warp owns a 32x32 C tile -> 32 acc regs/thread,
// no spills at the 64-reg cap; 2 CTAs/SM = 32 warps (50% occ).
// smem: [0,512) mask[128]; [512,+73728) 2 x 36864B stages (reused as Csh).
// =====================================================================
__global__ void __launch_bounds__(512, 2) k_mm(const float* __restrict__ maskp,
                                               const int* __restrict__ label) {
    extern __shared__ char sm_[];
    float* maskSh = (float*)sm_;
    char*  buf    = sm_ + 512;
    const int RS  = 144;
    const int ASZ = 128 * RS;     // 18432
    const int STG = 2 * ASZ;      // 36864 per stage

    int tid = threadIdx.x, lane = tid & 31, w = tid >> 5;
    int wm = w & 3, wn = w >> 2;               // 4 x 4 warp grid
    int bx = blockIdx.x, by = blockIdx.y;
    bool isB = (by >= NT2);
    int count = g_mcount;
    int jb = isB ? (by - NT2) * 128 : 0;

    if (isB && jb >= count) {                 // dead masked tile
        if (bx == 0) {
            int byb = by - NT2;
            for (int r = tid; r < Bsz; r += 512) g_s2b[(size_t)byb * Bsz + r] = 0.f;
            for (int i = tid; i < 2560; i += 512) g_t2b[(size_t)byb * 2560 + i] = -FLT_MAX;
        }
        return;
    }

    const __nv_bfloat16* gp = g_pbf + (size_t)bx * 128 * Dsz;
    const __nv_bfloat16* gq = isB ? (g_qm + (size_t)jb * Dsz)
                                  : (g_qbf + (size_t)by * 128 * Dsz);
    if (!isB && tid < 128) maskSh[tid] = maskp[by * 128 + tid];

    uint32_t sbase = (uint32_t)__cvta_generic_to_shared(buf);

    // closed-form copy offsets: i = tid + 512t -> c = tid&7 (const), r = (tid>>3)+64t
    const uint32_t off0 = (uint32_t)((tid >> 3) * RS + (tid & 7) * 16);      // +9216*t
    const uint32_t gof0 = (uint32_t)((tid >> 3) * 1024 + (tid & 7) * 16);    // +65536*t

    float acc[2][4][4];
    #pragma unroll
    for (int mt = 0; mt < 2; ++mt)
        #pragma unroll
        for (int nt = 0; nt < 4; ++nt)
            #pragma unroll
            for (int j = 0; j < 4; ++j) acc[mt][nt][j] = 0.f;

    auto issue = [&](int ks, int s) {
        uint32_t ab = sbase + s * STG + off0;
        uint32_t bb = ab + ASZ;
        const char* gA = (const char*)gp + ks * 128 + gof0;
        const char* gB = (const char*)gq + ks * 128 + gof0;
        #pragma unroll
        for (int t = 0; t < 2; ++t) {
            asm volatile("cp.async.cg.shared.global [%0],[%1],16;"
                         :: "r"(ab + t * 9216u), "l"(gA + t * 65536));
            asm volatile("cp.async.cg.shared.global [%0],[%1],16;"
                         :: "r"(bb + t * 9216u), "l"(gB + t * 65536));
        }
        asm volatile("cp.async.commit_group;");
    };

    auto compute = [&](int s) {
        uint32_t ab = sbase + s * STG;
        uint32_t bb = ab + ASZ;
        uint32_t aBase = ab + (wm * 32 + (lane & 15)) * RS + (lane >> 4) * 16;
        int bq = lane >> 3;
        uint32_t bPart = bb + (wn * 32 + (bq >> 1) * 8 + (lane & 7)) * RS + (bq & 1) * 16;
        #pragma unroll
        for (int kk = 0; kk < 4; ++kk) {
            uint32_t A[2][4];
            #pragma unroll
            for (int mt = 0; mt < 2; ++mt) {
                uint32_t ad = aBase + mt * 16 * RS + kk * 32;
                asm volatile("ldmatrix.sync.aligned.m8n8.x4.shared.b16 {%0,%1,%2,%3},[%4];"
                             : "=r"(A[mt][0]), "=r"(A[mt][1]), "=r"(A[mt][2]), "=r"(A[mt][3])
                             : "r"(ad));
            }
            #pragma unroll
            for (int np = 0; np < 2; ++np) {
                uint32_t bd = bPart + np * 16 * RS + kk * 32;
                uint32_t B0, B1, B2, B3;
                asm volatile("ldmatrix.sync.aligned.m8n8.x4.shared.b16 {%0,%1,%2,%3},[%4];"
                             : "=r"(B0), "=r"(B1), "=r"(B2), "=r"(B3) : "r"(bd));
                #pragma unroll
                for (int mt = 0; mt < 2; ++mt) {
                    MMA16816(acc[mt][2 * np],     A[mt], B0, B1);
                    MMA16816(acc[mt][2 * np + 1], A[mt], B2, B3);
                }
            }
        }
    };

    issue(0, 0);
    #pragma unroll 1
    for (int ks = 0; ks < 8; ++ks) {
        if (ks < 7) {
            issue(ks + 1, (ks + 1) & 1);
            asm volatile("cp.async.wait_group 1;");
        } else {
            asm volatile("cp.async.wait_group 0;");
        }
        __syncthreads();
        compute(ks & 1);
        __syncthreads();
    }

    // ---- C tile -> smem (68096 B <= 73728 B stage region) ----
    float* Csh = (float*)buf;
    #pragma unroll
    for (int mt = 0; mt < 2; ++mt)
        #pragma unroll
        for (int nt = 0; nt < 4; ++nt) {
            int r = wm * 32 + mt * 16 + (lane >> 2);
            int c = wn * 32 + nt * 8 + 2 * (lane & 3);
            Csh[r * CPAD + c]           = acc[mt][nt][0];
            Csh[r * CPAD + c + 1]       = acc[mt][nt][1];
            Csh[(r + 8) * CPAD + c]     = acc[mt][nt][2];
            Csh[(r + 8) * CPAD + c + 1] = acc[mt][nt][3];
        }
    __syncthreads();

    if (tid < 256) {
        if (!isB) {
            // tid<128: s1 (all cols) + top10 all; tid>=128: s1m (masked) + top10 unmasked
            int  r     = tid & 127;
            bool roleB = (tid >= 128);
            int  gb    = bx * 128 + r;
            bool neg   = (label[gb] == -1);

            float s = 0.f;
            float top[10];
            #pragma unroll
            for (int i = 0; i < 10; ++i) top[i] = -FLT_MAX;

            const float* Crow = Csh + r * CPAD;
            for (int c = 0; c < 128; ++c) {
                float v = Crow[c];
                bool  mskd = (maskSh[c] != 0.f);
                if (!roleB) {
                    s += ex2f(K2f * v);
                    if (neg) ins10(top, v);
                } else {
                    if (mskd) s += ex2f(K2f * v);
                    else if (neg) ins10(top, v);
                }
            }

            size_t si = (size_t)by * Bsz + gb;
            if (!roleB) g_s1[si] = s; else g_s1m[si] = s;
            if (neg) {
                size_t ti = ((size_t)by * 256 + (gb >> 2)) * 10;
                float* gt_ = roleB ? g_t1u : g_t1;
                #pragma unroll
                for (int i = 0; i < 10; ++i) gt_[ti + i] = top[i];
            }
        } else if (tid < 128) {
            int  byb = by - NT2;
            int  r   = tid;
            int  gb  = bx * 128 + r;
            bool neg = (label[gb] == -1);
            int  nvalid = count - jb; if (nvalid > 128) nvalid = 128;

            float s = 0.f;
            float top[10];
            #pragma unroll
            for (int i = 0; i < 10; ++i) top[i] = -FLT_MAX;

            const float* Crow = Csh + r * CPAD;
            for (int c = 0; c < nvalid; ++c) {
                float v = Crow[c];
                s += ex2f(K2f * v);
                if (neg) ins10(top, v);
            }
            g_s2b[(size_t)byb * Bsz + gb] = s;
            if (neg) {
                size_t ti = ((size_t)byb * 256 + (gb >> 2)) * 10;
                #pragma unroll
                for (int i = 0; i < 10; ++i) g_t2b[ti + i] = top[i];
            }
        }
    }
}

// =====================================================================
// Pass 2: per-row merge
// =====================================================================
__global__ void __launch_bounds__(256) k_pass2(const float* __restrict__ p,
                                               const float* __restrict__ q,
                                               const float* __restrict__ maskp,
                                               const int* __restrict__ label) {
    __shared__ float red[256];
    __shared__ float red2[256];
    __shared__ float red3[256];
    __shared__ float cand[2560];
    __shared__ float wv_[8];
    __shared__ int   wi_[8];

    int b = blockIdx.x, tid = threadIdx.x;
    int lab = label[b];

    if (lab != -1) {
        float s1 = 0.f, s1m = 0.f, s2b = 0.f;
        for (int t = tid; t < NT2; t += 256) {
            s1  += g_s1 [(size_t)t * Bsz + b];
            s1m += g_s1m[(size_t)t * Bsz + b];
            if (t < MT2) s2b += g_s2b[(size_t)t * Bsz + b];
        }
        red[tid] = s1; red2[tid] = s1m; red3[tid] = s2b;
        __syncthreads();
        for (int o = 128; o > 0; o >>= 1) {
            if (tid < o) {
                red[tid]  += red[tid + o];
                red2[tid] += red2[tid + o];
                red3[tid] += red3[tid + o];
            }
            __syncthreads();
        }
        float S1 = red[0];
        float S2 = red[0] - red2[0] + red3[0];
        __syncthreads();

        float d1 = 0.f, d2 = 0.f;
        float mk = maskp[lab];
        const float* pr = p + (size_t)b * Dsz;
        const float* q0 = q + (size_t)lab * Dsz;
        const float* q1 = q0 + (size_t)Qsz * Dsz;
        for (int d = tid; d < Dsz; d += 256) {
            float pv = pr[d], a0 = q0[d], a1 = q1[d];
            float wv = mk * a1 + (1.f - mk) * a0;
            d1 += pv * a0;
            d2 += pv * wv;
        }
        red[tid] = d1; red2[tid] = d2;
        __syncthreads();
        for (int o = 128; o > 0; o >>= 1) {
            if (tid < o) { red[tid] += red[tid + o]; red2[tid] += red2[tid + o]; }
            __syncthreads();
        }
        if (tid == 0) {
            float gt1 = red[0], gt2 = red2[0];
            float sp1 = S1 - ex2f(K2f * gt1) + ex2f(K2f * (gt1 - MARGINf));
            float sp2 = S2 - ex2f(K2f * gt2) + ex2f(K2f * (gt2 - MARGINf));
            float ce1 = logf(sp1) - (gt1 - MARGINf) * SCALEf;
            float ce2 = logf(sp2) - (gt2 - MARGINf) * SCALEf;
            g_row[b] = ce1 + ce2;
        }
    } else {
        float negsum = 0.f;
        size_t base = (size_t)(b >> 2) * 10;
        for (int mat = 0; mat < 2; ++mat) {
            float top[10];
            #pragma unroll
            for (int i = 0; i < 10; ++i) top[i] = -FLT_MAX;
            int nlists = (mat == 0) ? NT2 : (NT2 + MT2);
            for (int t = tid; t < nlists; t += 256) {
                const float* L;
                if (mat == 0)        L = g_t1  + (size_t)t * 2560 + base;
                else if (t < NT2)    L = g_t1u + (size_t)t * 2560 + base;
                else                 L = g_t2b + (size_t)(t - NT2) * 2560 + base;
                #pragma unroll
                for (int i = 0; i < 10; ++i) {
                    float v = L[i];
                    if (v <= top[9]) break;   // lists sorted descending
                    ins10(top, v);
                }
            }
            #pragma unroll
            for (int i = 0; i < 10; ++i) cand[tid * 10 + i] = top[i];
            __syncthreads();

            for (int it = 0; it < 10; ++it) {
                float bv = -FLT_MAX; int bi = -1;
                #pragma unroll
                for (int j = 0; j < 10; ++j) {
                    float v = cand[tid * 10 + j];
                    if (v > bv) { bv = v; bi = tid * 10 + j; }
                }
                #pragma unroll
                for (int o = 16; o > 0; o >>= 1) {
                    float ov = __shfl_down_sync(0xffffffffu, bv, o);
                    int   oi = __shfl_down_sync(0xffffffffu, bi, o);
                    if (ov > bv) { bv = ov; bi = oi; }
                }
                if ((tid & 31) == 0) { wv_[tid >> 5] = bv; wi_[tid >> 5] = bi; }
                __syncthreads();
                if (tid == 0) {
                    float mv = wv_[0]; int mi = wi_[0];
                    #pragma unroll
                    for (int k = 1; k < 8; ++k)
                        if (wv_[k] > mv) { mv = wv_[k]; mi = wi_[k]; }
                    cand[mi] = -FLT_MAX;
                    negsum += fmaxf(mv, 0.f);
                }
                __syncthreads();
            }
            __syncthreads();
        }
        if (tid == 0) g_row[b] = negsum * 0.1f;
    }
}

// =====================================================================
// Pass 3: scalar reduction
// =====================================================================
__global__ void k_final(const int* __restrict__ label, float* __restrict__ out) {
    __shared__ float sp[256], sn[256];
    __shared__ int   cp_[256], cn_[256];
    int tid = threadIdx.x;
    float ps = 0.f, ns = 0.f;
    int pc = 0, nc = 0;
    for (int b = tid; b < Bsz; b += 256) {
        if (label[b] != -1) { ps += g_row[b]; pc++; }
        else                { ns += g_row[b]; nc++; }
    }
    sp[tid] = ps; sn[tid] = ns; cp_[tid] = pc; cn_[tid] = nc;
    __syncthreads();
    for (int o = 128; o > 0; o >>= 1) {
        if (tid < o) {
            sp[tid] += sp[tid + o]; sn[tid] += sn[tid + o];
            cp_[tid] += cp_[tid + o]; cn_[tid] += cn_[tid + o];
        }
        __syncthreads();
    }
    if (tid == 0) {
        float r = 0.f;
        if (cp_[0] > 0) r += sp[0] / (float)cp_[0];
        if (cn_[0] > 0) r += sn[0] / (float)cn_[0];
        out[0] = r;
    }
}

// =====================================================================
extern "C" void kernel_launch(void* const* d_in, const int* in_sizes, int n_in,
                              void* d_out, int out_size) {
    const float* p   = (const float*)d_in[0];
    const float* q   = (const float*)d_in[1];
    const float* mk  = (const float*)d_in[2];
    const int*   lab = (const int*)d_in[3];
    float* out = (float*)d_out;

    const int SMEM1 = 512 + 2 * 36864;   // 74240
    cudaFuncSetAttribute(k_mm, cudaFuncAttributeMaxDynamicSharedMemorySize, SMEM1);

    k_convert<<<33280, 256>>>(p, q);
    k_scan<<<1, 1024>>>(mk);
    k_gather<<<MCAP, 128>>>(q);
    dim3 g1(8, NT2 + MT2);
    k_mm<<<g1, 512, SMEM1>>>(mk, lab);
    k_pass2<<<Bsz, 256>>>(p, q, mk, lab);
    k_final<<<1, 256>>>(lab, out);
}

// round 13
// speedup vs baseline: 1.1900x; 1.0168x over previous
#include <cuda_runtime.h>
#include <cuda_bf16.h>
#include <cstdint>
#include <cfloat>
#include <math.h>

#define Bsz 1024
#define Qsz 65536
#define Dsz 512
#define MARGINf 0.4f
#define SCALEf 32.0f
#define K2f 46.166241308446828f   /* 32*log2(e) */
#define NT2 512                   /* q-tiles of 128 slots (q0 GEMM) */
#define MT2 64                    /* masked-compact tiles of 128 */
#define MCAP 8192
#define CPAD 133

// ---------------- static device scratch (no allocations) ----------------
__device__ __align__(16) __nv_bfloat16 g_qbf[(size_t)Qsz * Dsz];     // q0 bf16, 64 MB
__device__ __align__(16) __nv_bfloat16 g_pbf[Bsz * Dsz];             // 1 MB
__device__ __align__(16) __nv_bfloat16 g_qm[(size_t)MCAP * Dsz];     // masked q1 rows, 8 MB
__device__ int   g_midx[MCAP];
__device__ int   g_mcount;
__device__ float g_s1 [(size_t)NT2 * Bsz];
__device__ float g_s1m[(size_t)NT2 * Bsz];
__device__ float g_s2b[(size_t)MT2 * Bsz];
__device__ float g_t1 [(size_t)NT2 * 256 * 10];
__device__ float g_t1u[(size_t)NT2 * 256 * 10];
__device__ float g_t2b[(size_t)MT2 * 256 * 10];
__device__ float g_row[Bsz];

// ---------------- helpers ----------------
__device__ __forceinline__ float ex2f(float x) {
    float y;
    asm("ex2.approx.ftz.f32 %0, %1;" : "=f"(y) : "f"(x));
    return y;
}

__device__ __forceinline__ void ins10(float (&t)[10], float v) {
    if (v <= t[9]) return;
    #pragma unroll
    for (int i = 0; i < 10; ++i) {
        float a  = t[i];
        float hi = fmaxf(a, v);
        float lo = fminf(a, v);
        t[i] = hi;
        v    = lo;
    }
}

#define MMA16816(ac, Ar, b0, b1)                                                        \
    asm volatile(                                                                       \
        "mma.sync.aligned.m16n8k16.row.col.f32.bf16.bf16.f32 "                          \
        "{%0,%1,%2,%3},{%4,%5,%6,%7},{%8,%9},{%0,%1,%2,%3};"                            \
        : "+f"(ac[0]), "+f"(ac[1]), "+f"(ac[2]), "+f"(ac[3])                            \
        : "r"(Ar[0]), "r"(Ar[1]), "r"(Ar[2]), "r"(Ar[3]), "r"(b0), "r"(b1))

// =====================================================================
// Pass 0a: fp32 -> bf16 staging for p and queue[0]
// =====================================================================
__global__ void k_convert(const float* __restrict__ p, const float* __restrict__ q) {
    int i = blockIdx.x * blockDim.x + threadIdx.x;
    const int PN4 = (Bsz * Dsz) / 4;
    const int TOT = PN4 + (Qsz * Dsz) / 4;
    if (i >= TOT) return;
    float4 v;
    __nv_bfloat162* dst;
    if (i < PN4) {
        v   = ((const float4*)p)[i];
        dst = (__nv_bfloat162*)g_pbf + (size_t)i * 2;
    } else {
        size_t j = (size_t)i - PN4;
        v   = ((const float4*)q)[j];
        dst = (__nv_bfloat162*)g_qbf + j * 2;
    }
    dst[0] = __floats2bfloat162_rn(v.x, v.y);
    dst[1] = __floats2bfloat162_rn(v.z, v.w);
}

// =====================================================================
// Pass 0b: compact masked slot indices — coalesced strided access.
// =====================================================================
__global__ void __launch_bounds__(1024) k_scan(const float* __restrict__ maskp) {
    __shared__ int cnt[1024];
    int t = threadIdx.x;
    int local = 0;
    #pragma unroll 4
    for (int i = 0; i < 64; ++i) local += (maskp[i * 1024 + t] != 0.f);
    cnt[t] = local;
    __syncthreads();
    for (int o = 1; o < 1024; o <<= 1) {
        int v = (t >= o) ? cnt[t - o] : 0;
        __syncthreads();
        cnt[t] += v;
        __syncthreads();
    }
    if (t == 1023) g_mcount = cnt[1023] < MCAP ? cnt[1023] : MCAP;
    int j = cnt[t] - local;
    for (int i = 0; i < 64; ++i) {
        int idx = i * 1024 + t;
        if (maskp[idx] != 0.f) {
            if (j < MCAP) g_midx[j] = idx;
            ++j;
        }
    }
}

// =====================================================================
// Pass 0c: gather+convert masked q1 rows (zero-fill beyond count)
// =====================================================================
__global__ void __launch_bounds__(128) k_gather(const float* __restrict__ q) {
    int j = blockIdx.x, t = threadIdx.x;
    int count = g_mcount;
    __nv_bfloat162* dst = (__nv_bfloat162*)(g_qm + (size_t)j * Dsz);
    if (j < count) {
        const float4* src =
            (const float4*)(q + (size_t)Qsz * Dsz + (size_t)g_midx[j] * Dsz);
        float4 v = src[t];
        dst[t * 2]     = __floats2bfloat162_rn(v.x, v.y);
        dst[t * 2 + 1] = __floats2bfloat162_rn(v.z, v.w);
    } else {
        __nv_bfloat162 z = __floats2bfloat162_rn(0.f, 0.f);
        dst[t * 2]     = z;
        dst[t * 2 + 1] = z;
    }
}

// =====================================================================
// Merged Pass 1 + 1b: bf16 GEMM (128x128xK512) + fused epilogue.
// grid (8 b-tiles [fast], 512 q0-tiles + 64 masked tiles), 512 threads.
// 16 warps (4x4), each 32x32 of C. XOR-128B swizzled smem (conflict-free
// LDSM), 3-stage cp.async, ONE barrier per K-step.
// smem: [0,512) mask[128]; [512,+98304) 3 x 32768B stages (reused as Csh).
// =====================================================================
__global__ void __launch_bounds__(512, 2) k_mm(const float* __restrict__ maskp,
                                               const int* __restrict__ label) {
    extern __shared__ char sm_[];
    float* maskSh = (float*)sm_;
    char*  buf    = sm_ + 512;
    const int ASZ = 128 * 128;    // 16384 per tile
    const int STG = 2 * ASZ;      // 32768 per stage (A + B)

    int tid = threadIdx.x, lane = tid & 31, w = tid >> 5;
    int wm = w & 3, wn = w >> 2;               // 4 x 4 warp grid
    int bx = blockIdx.x, by = blockIdx.y;
    bool isB = (by >= NT2);
    int count = g_mcount;
    int jb = isB ? (by - NT2) * 128 : 0;

    if (isB && jb >= count) {                 // dead masked tile
        if (bx == 0) {
            int byb = by - NT2;
            for (int r = tid; r < Bsz; r += 512) g_s2b[(size_t)byb * Bsz + r] = 0.f;
            for (int i = tid; i < 2560; i += 512) g_t2b[(size_t)byb * 2560 + i] = -FLT_MAX;
        }
        return;
    }

    const __nv_bfloat16* gp = g_pbf + (size_t)bx * 128 * Dsz;
    const __nv_bfloat16* gq = isB ? (g_qm + (size_t)jb * Dsz)
                                  : (g_qbf + (size_t)by * 128 * Dsz);
    if (!isB && tid < 128) maskSh[tid] = maskp[by * 128 + tid];

    uint32_t sbase = (uint32_t)__cvta_generic_to_shared(buf);

    // cp.async: thread writes 16B at row r=(tid>>3)+64t, chunk c=tid&7.
    // Swizzle: chunk' = c ^ (r&7); r&7 invariant under +64 -> constant.
    const uint32_t off0 =
        (uint32_t)(((tid >> 3) << 7) + ((((tid & 7) ^ ((tid >> 3) & 7))) << 4)); // +8192*t
    const uint32_t gof0 = (uint32_t)((tid >> 3) * 1024 + (tid & 7) * 16);        // +65536*t

    float acc[2][4][4];
    #pragma unroll
    for (int mt = 0; mt < 2; ++mt)
        #pragma unroll
        for (int nt = 0; nt < 4; ++nt)
            #pragma unroll
            for (int j = 0; j < 4; ++j) acc[mt][nt][j] = 0.f;

    auto issue = [&](int ks, int s) {
        uint32_t ab = sbase + s * STG + off0;
        uint32_t bb = ab + ASZ;
        const char* gA = (const char*)gp + ks * 128 + gof0;
        const char* gB = (const char*)gq + ks * 128 + gof0;
        #pragma unroll
        for (int t = 0; t < 2; ++t) {
            asm volatile("cp.async.cg.shared.global [%0],[%1],16;"
                         :: "r"(ab + t * 8192u), "l"(gA + t * 65536));
            asm volatile("cp.async.cg.shared.global [%0],[%1],16;"
                         :: "r"(bb + t * 8192u), "l"(gB + t * 65536));
        }
        asm volatile("cp.async.commit_group;");
    };

    // LDSM row constants (low-3-bits invariant across mt/np offsets)
    const int rA  = wm * 32 + (lane & 15);
    const uint32_t a7  = (uint32_t)(rA & 7);
    const uint32_t aRowOff = (uint32_t)(rA << 7);          // +2048 per mt
    const int cA0 = lane >> 4;                             // + 2*kk
    const int bq  = lane >> 3;
    const int rB  = wn * 32 + ((bq >> 1) << 3) + (lane & 7);
    const uint32_t b7  = (uint32_t)(lane & 7);
    const uint32_t bRowOff = (uint32_t)(rB << 7);          // +2048 per np
    const int cB0 = bq & 1;

    auto compute = [&](int s) {
        uint32_t ab = sbase + s * STG + aRowOff;
        uint32_t bb = sbase + s * STG + ASZ + bRowOff;
        #pragma unroll
        for (int kk = 0; kk < 4; ++kk) {
            uint32_t cA = (uint32_t)(cA0 + 2 * kk) ^ a7;
            uint32_t cB = (uint32_t)(cB0 + 2 * kk) ^ b7;
            uint32_t A[2][4];
            #pragma unroll
            for (int mt = 0; mt < 2; ++mt) {
                uint32_t ad = ab + mt * 2048u + (cA << 4);
                asm volatile("ldmatrix.sync.aligned.m8n8.x4.shared.b16 {%0,%1,%2,%3},[%4];"
                             : "=r"(A[mt][0]), "=r"(A[mt][1]), "=r"(A[mt][2]), "=r"(A[mt][3])
                             : "r"(ad));
            }
            #pragma unroll
            for (int np = 0; np < 2; ++np) {
                uint32_t bd = bb + np * 2048u + (cB << 4);
                uint32_t B0, B1, B2, B3;
                asm volatile("ldmatrix.sync.aligned.m8n8.x4.shared.b16 {%0,%1,%2,%3},[%4];"
                             : "=r"(B0), "=r"(B1), "=r"(B2), "=r"(B3) : "r"(bd));
                #pragma unroll
                for (int mt = 0; mt < 2; ++mt) {
                    MMA16816(acc[mt][2 * np],     A[mt], B0, B1);
                    MMA16816(acc[mt][2 * np + 1], A[mt], B2, B3);
                }
            }
        }
    };

    // 3-stage pipeline, ONE barrier per K-step
    issue(0, 0);
    issue(1, 1);
    #pragma unroll 1
    for (int ks = 0; ks < 8; ++ks) {
        int s = ks % 3;
        if (ks < 7) asm volatile("cp.async.wait_group 1;");
        else        asm volatile("cp.async.wait_group 0;");
        __syncthreads();
        compute(s);
        if (ks < 6) issue(ks + 2, (ks + 2) % 3);
    }
    __syncthreads();   // all compute done before Csh reuse

    // ---- C tile -> smem (68096 B <= 98304 B stage region) ----
    float* Csh = (float*)buf;
    #pragma unroll
    for (int mt = 0; mt < 2; ++mt)
        #pragma unroll
        for (int nt = 0; nt < 4; ++nt) {
            int r = wm * 32 + mt * 16 + (lane >> 2);
            int c = wn * 32 + nt * 8 + 2 * (lane & 3);
            Csh[r * CPAD + c]           = acc[mt][nt][0];
            Csh[r * CPAD + c + 1]       = acc[mt][nt][1];
            Csh[(r + 8) * CPAD + c]     = acc[mt][nt][2];
            Csh[(r + 8) * CPAD + c + 1] = acc[mt][nt][3];
        }
    __syncthreads();

    if (tid < 256) {
        if (!isB) {
            int  r     = tid & 127;
            bool roleB = (tid >= 128);
            int  gb    = bx * 128 + r;
            bool neg   = (label[gb] == -1);

            float s = 0.f;
            float top[10];
            #pragma unroll
            for (int i = 0; i < 10; ++i) top[i] = -FLT_MAX;

            const float* Crow = Csh + r * CPAD;
            for (int c = 0; c < 128; ++c) {
                float v = Crow[c];
                bool  mskd = (maskSh[c] != 0.f);
                if (!roleB) {
                    s += ex2f(K2f * v);
                    if (neg) ins10(top, v);
                } else {
                    if (mskd) s += ex2f(K2f * v);
                    else if (neg) ins10(top, v);
                }
            }

            size_t si = (size_t)by * Bsz + gb;
            if (!roleB) g_s1[si] = s; else g_s1m[si] = s;
            if (neg) {
                size_t ti = ((size_t)by * 256 + (gb >> 2)) * 10;
                float* gt_ = roleB ? g_t1u : g_t1;
                #pragma unroll
                for (int i = 0; i < 10; ++i) gt_[ti + i] = top[i];
            }
        } else if (tid < 128) {
            int  byb = by - NT2;
            int  r   = tid;
            int  gb  = bx * 128 + r;
            bool neg = (label[gb] == -1);
            int  nvalid = count - jb; if (nvalid > 128) nvalid = 128;

            float s = 0.f;
            float top[10];
            #pragma unroll
            for (int i = 0; i < 10; ++i) top[i] = -FLT_MAX;

            const float* Crow = Csh + r * CPAD;
            for (int c = 0; c < nvalid; ++c) {
                float v = Crow[c];
                s += ex2f(K2f * v);
                if (neg) ins10(top, v);
            }
            g_s2b[(size_t)byb * Bsz + gb] = s;
            if (neg) {
                size_t ti = ((size_t)byb * 256 + (gb >> 2)) * 10;
                #pragma unroll
                for (int i = 0; i < 10; ++i) g_t2b[ti + i] = top[i];
            }
        }
    }
}

// =====================================================================
// Pass 2: per-row merge
// =====================================================================
__global__ void __launch_bounds__(256) k_pass2(const float* __restrict__ p,
                                               const float* __restrict__ q,
                                               const float* __restrict__ maskp,
                                               const int* __restrict__ label) {
    __shared__ float red[256];
    __shared__ float red2[256];
    __shared__ float red3[256];
    __shared__ float cand[2560];
    __shared__ float wv_[8];
    __shared__ int   wi_[8];

    int b = blockIdx.x, tid = threadIdx.x;
    int lab = label[b];

    if (lab != -1) {
        float s1 = 0.f, s1m = 0.f, s2b = 0.f;
        for (int t = tid; t < NT2; t += 256) {
            s1  += g_s1 [(size_t)t * Bsz + b];
            s1m += g_s1m[(size_t)t * Bsz + b];
            if (t < MT2) s2b += g_s2b[(size_t)t * Bsz + b];
        }
        red[tid] = s1; red2[tid] = s1m; red3[tid] = s2b;
        __syncthreads();
        for (int o = 128; o > 0; o >>= 1) {
            if (tid < o) {
                red[tid]  += red[tid + o];
                red2[tid] += red2[tid + o];
                red3[tid] += red3[tid + o];
            }
            __syncthreads();
        }
        float S1 = red[0];
        float S2 = red[0] - red2[0] + red3[0];
        __syncthreads();

        float d1 = 0.f, d2 = 0.f;
        float mk = maskp[lab];
        const float* pr = p + (size_t)b * Dsz;
        const float* q0 = q + (size_t)lab * Dsz;
        const float* q1 = q0 + (size_t)Qsz * Dsz;
        for (int d = tid; d < Dsz; d += 256) {
            float pv = pr[d], a0 = q0[d], a1 = q1[d];
            float wv = mk * a1 + (1.f - mk) * a0;
            d1 += pv * a0;
            d2 += pv * wv;
        }
        red[tid] = d1; red2[tid] = d2;
        __syncthreads();
        for (int o = 128; o > 0; o >>= 1) {
            if (tid < o) { red[tid] += red[tid + o]; red2[tid] += red2[tid + o]; }
            __syncthreads();
        }
        if (tid == 0) {
            float gt1 = red[0], gt2 = red2[0];
            float sp1 = S1 - ex2f(K2f * gt1) + ex2f(K2f * (gt1 - MARGINf));
            float sp2 = S2 - ex2f(K2f * gt2) + ex2f(K2f * (gt2 - MARGINf));
            float ce1 = logf(sp1) - (gt1 - MARGINf) * SCALEf;
            float ce2 = logf(sp2) - (gt2 - MARGINf) * SCALEf;
            g_row[b] = ce1 + ce2;
        }
    } else {
        float negsum = 0.f;
        size_t base = (size_t)(b >> 2) * 10;
        for (int mat = 0; mat < 2; ++mat) {
            float top[10];
            #pragma unroll
            for (int i = 0; i < 10; ++i) top[i] = -FLT_MAX;
            int nlists = (mat == 0) ? NT2 : (NT2 + MT2);
            for (int t = tid; t < nlists; t += 256) {
                const float* L;
                if (mat == 0)        L = g_t1  + (size_t)t * 2560 + base;
                else if (t < NT2)    L = g_t1u + (size_t)t * 2560 + base;
                else                 L = g_t2b + (size_t)(t - NT2) * 2560 + base;
                #pragma unroll
                for (int i = 0; i < 10; ++i) {
                    float v = L[i];
                    if (v <= top[9]) break;   // lists sorted descending
                    ins10(top, v);
                }
            }
            #pragma unroll
            for (int i = 0; i < 10; ++i) cand[tid * 10 + i] = top[i];
            __syncthreads();

            for (int it = 0; it < 10; ++it) {
                float bv = -FLT_MAX; int bi = -1;
                #pragma unroll
                for (int j = 0; j < 10; ++j) {
                    float v = cand[tid * 10 + j];
                    if (v > bv) { bv = v; bi = tid * 10 + j; }
                }
                #pragma unroll
                for (int o = 16; o > 0; o >>= 1) {
                    float ov = __shfl_down_sync(0xffffffffu, bv, o);
                    int   oi = __shfl_down_sync(0xffffffffu, bi, o);
                    if (ov > bv) { bv = ov; bi = oi; }
                }
                if ((tid & 31) == 0) { wv_[tid >> 5] = bv; wi_[tid >> 5] = bi; }
                __syncthreads();
                if (tid == 0) {
                    float mv = wv_[0]; int mi = wi_[0];
                    #pragma unroll
                    for (int k = 1; k < 8; ++k)
                        if (wv_[k] > mv) { mv = wv_[k]; mi = wi_[k]; }
                    cand[mi] = -FLT_MAX;
                    negsum += fmaxf(mv, 0.f);
                }
                __syncthreads();
            }
            __syncthreads();
        }
        if (tid == 0) g_row[b] = negsum * 0.1f;
    }
}

// =====================================================================
// Pass 3: scalar reduction
// =====================================================================
__global__ void k_final(const int* __restrict__ label, float* __restrict__ out) {
    __shared__ float sp[256], sn[256];
    __shared__ int   cp_[256], cn_[256];
    int tid = threadIdx.x;
    float ps = 0.f, ns = 0.f;
    int pc = 0, nc = 0;
    for (int b = tid; b < Bsz; b += 256) {
        if (label[b] != -1) { ps += g_row[b]; pc++; }
        else                { ns += g_row[b]; nc++; }
    }
    sp[tid] = ps; sn[tid] = ns; cp_[tid] = pc; cn_[tid] = nc;
    __syncthreads();
    for (int o = 128; o > 0; o >>= 1) {
        if (tid < o) {
            sp[tid] += sp[tid + o]; sn[tid] += sn[tid + o];
            cp_[tid] += cp_[tid + o]; cn_[tid] += cn_[tid + o];
        }
        __syncthreads();
    }
    if (tid == 0) {
        float r = 0.f;
        if (cp_[0] > 0) r += sp[0] / (float)cp_[0];
        if (cn_[0] > 0) r += sn[0] / (float)cn_[0];
        out[0] = r;
    }
}

// =====================================================================
extern "C" void kernel_launch(void* const* d_in, const int* in_sizes, int n_in,
                              void* d_out, int out_size) {
    const float* p   = (const float*)d_in[0];
    const float* q   = (const float*)d_in[1];
    const float* mk  = (const float*)d_in[2];
    const int*   lab = (const int*)d_in[3];
    float* out = (float*)d_out;

    const int SMEM1 = 512 + 3 * 32768;   // 98816 (2 CTAs/SM: 197632 <= 228KB)
    cudaFuncSetAttribute(k_mm, cudaFuncAttributeMaxDynamicSharedMemorySize, SMEM1);

    k_convert<<<33280, 256>>>(p, q);
    k_scan<<<1, 1024>>>(mk);
    k_gather<<<MCAP, 128>>>(q);
    dim3 g1(8, NT2 + MT2);
    k_mm<<<g1, 512, SMEM1>>>(mk, lab);
    k_pass2<<<Bsz, 256>>>(p, q, mk, lab);
    k_final<<<1, 256>>>(lab, out);
}

// round 14
// speedup vs baseline: 1.2969x; 1.0899x over previous
#include <cuda_runtime.h>
#include <cuda_bf16.h>
#include <cstdint>
#include <cfloat>
#include <math.h>

#define Bsz 1024
#define Qsz 65536
#define Dsz 512
#define MARGINf 0.4f
#define SCALEf 32.0f
#define K2f 46.166241308446828f   /* 32*log2(e) */
#define NT2 512                   /* q-tiles of 128 slots (q0 GEMM) */
#define MT2 64                    /* masked-compact tiles of 128 */
#define MCAP 8192
#define CPAD 133

// ---------------- static device scratch (no allocations) ----------------
__device__ __align__(16) __nv_bfloat16 g_qbf[(size_t)Qsz * Dsz];     // q0 bf16, 64 MB
__device__ __align__(16) __nv_bfloat16 g_pbf[Bsz * Dsz];             // 1 MB
__device__ __align__(16) __nv_bfloat16 g_qm[(size_t)MCAP * Dsz];     // masked q1 rows, 8 MB
__device__ int   g_midx[MCAP];
__device__ int   g_mcount;
__device__ float g_s1 [(size_t)NT2 * Bsz];
__device__ float g_s1m[(size_t)NT2 * Bsz];
__device__ float g_s2b[(size_t)MT2 * Bsz];
__device__ float g_t1 [(size_t)NT2 * 256 * 10];
__device__ float g_t1u[(size_t)NT2 * 256 * 10];
__device__ float g_t2b[(size_t)MT2 * 256 * 10];
__device__ float g_row[Bsz];

// ---------------- helpers ----------------
__device__ __forceinline__ float ex2f(float x) {
    float y;
    asm("ex2.approx.ftz.f32 %0, %1;" : "=f"(y) : "f"(x));
    return y;
}

__device__ __forceinline__ void ins10(float (&t)[10], float v) {
    if (v <= t[9]) return;
    #pragma unroll
    for (int i = 0; i < 10; ++i) {
        float a  = t[i];
        float hi = fmaxf(a, v);
        float lo = fminf(a, v);
        t[i] = hi;
        v    = lo;
    }
}

#define MMA16816(ac, Ar, b0, b1)                                                        \
    asm volatile(                                                                       \
        "mma.sync.aligned.m16n8k16.row.col.f32.bf16.bf16.f32 "                          \
        "{%0,%1,%2,%3},{%4,%5,%6,%7},{%8,%9},{%0,%1,%2,%3};"                            \
        : "+f"(ac[0]), "+f"(ac[1]), "+f"(ac[2]), "+f"(ac[3])                            \
        : "r"(Ar[0]), "r"(Ar[1]), "r"(Ar[2]), "r"(Ar[3]), "r"(b0), "r"(b1))

// =====================================================================
// Pass 0a: fp32 -> bf16 staging for p and queue[0]
// =====================================================================
__global__ void k_convert(const float* __restrict__ p, const float* __restrict__ q) {
    int i = blockIdx.x * blockDim.x + threadIdx.x;
    const int PN4 = (Bsz * Dsz) / 4;
    const int TOT = PN4 + (Qsz * Dsz) / 4;
    if (i >= TOT) return;
    float4 v;
    __nv_bfloat162* dst;
    if (i < PN4) {
        v   = ((const float4*)p)[i];
        dst = (__nv_bfloat162*)g_pbf + (size_t)i * 2;
    } else {
        size_t j = (size_t)i - PN4;
        v   = ((const float4*)q)[j];
        dst = (__nv_bfloat162*)g_qbf + j * 2;
    }
    dst[0] = __floats2bfloat162_rn(v.x, v.y);
    dst[1] = __floats2bfloat162_rn(v.z, v.w);
}

// =====================================================================
// Pass 0b: compact masked slot indices — coalesced strided access.
// =====================================================================
__global__ void __launch_bounds__(1024) k_scan(const float* __restrict__ maskp) {
    __shared__ int cnt[1024];
    int t = threadIdx.x;
    int local = 0;
    #pragma unroll 4
    for (int i = 0; i < 64; ++i) local += (maskp[i * 1024 + t] != 0.f);
    cnt[t] = local;
    __syncthreads();
    for (int o = 1; o < 1024; o <<= 1) {
        int v = (t >= o) ? cnt[t - o] : 0;
        __syncthreads();
        cnt[t] += v;
        __syncthreads();
    }
    if (t == 1023) g_mcount = cnt[1023] < MCAP ? cnt[1023] : MCAP;
    int j = cnt[t] - local;
    for (int i = 0; i < 64; ++i) {
        int idx = i * 1024 + t;
        if (maskp[idx] != 0.f) {
            if (j < MCAP) g_midx[j] = idx;
            ++j;
        }
    }
}

// =====================================================================
// Pass 0c: gather+convert masked q1 rows (zero-fill beyond count)
// =====================================================================
__global__ void __launch_bounds__(128) k_gather(const float* __restrict__ q) {
    int j = blockIdx.x, t = threadIdx.x;
    int count = g_mcount;
    __nv_bfloat162* dst = (__nv_bfloat162*)(g_qm + (size_t)j * Dsz);
    if (j < count) {
        const float4* src =
            (const float4*)(q + (size_t)Qsz * Dsz + (size_t)g_midx[j] * Dsz);
        float4 v = src[t];
        dst[t * 2]     = __floats2bfloat162_rn(v.x, v.y);
        dst[t * 2 + 1] = __floats2bfloat162_rn(v.z, v.w);
    } else {
        __nv_bfloat162 z = __floats2bfloat162_rn(0.f, 0.f);
        dst[t * 2]     = z;
        dst[t * 2 + 1] = z;
    }
}

// =====================================================================
// Merged Pass 1 + 1b: bf16 GEMM (128x128xK512) + register-level epilogue.
// grid (8 b-tiles [fast], 512 q0-tiles + 64 masked tiles), 512 threads.
// 16 warps (4x4), each 32x32 of C. XOR-128B swizzled smem, 3-stage cp.async.
// Epilogue: sumexp computed from accumulator registers (shfl + 4KB smem
// combine); Csh round-trip only for top-10 on negative rows.
// smem: [0,512) mask[128]; buf: 3 x 32768B stages
//       (reused: Csh @0..68096, rowsum arrays @69632..73728).
// =====================================================================
__global__ void __launch_bounds__(512, 2) k_mm(const float* __restrict__ maskp,
                                               const int* __restrict__ label) {
    extern __shared__ char sm_[];
    float* maskSh = (float*)sm_;
    char*  buf    = sm_ + 512;
    const int ASZ = 128 * 128;    // 16384 per tile
    const int STG = 2 * ASZ;      // 32768 per stage (A + B)

    int tid = threadIdx.x, lane = tid & 31, w = tid >> 5;
    int wm = w & 3, wn = w >> 2;               // 4 x 4 warp grid
    int bx = blockIdx.x, by = blockIdx.y;
    bool isB = (by >= NT2);
    int count = g_mcount;
    int jb = isB ? (by - NT2) * 128 : 0;

    if (isB && jb >= count) {                 // dead masked tile
        if (bx == 0) {
            int byb = by - NT2;
            for (int r = tid; r < Bsz; r += 512) g_s2b[(size_t)byb * Bsz + r] = 0.f;
            for (int i = tid; i < 2560; i += 512) g_t2b[(size_t)byb * 2560 + i] = -FLT_MAX;
        }
        return;
    }

    const __nv_bfloat16* gp = g_pbf + (size_t)bx * 128 * Dsz;
    const __nv_bfloat16* gq = isB ? (g_qm + (size_t)jb * Dsz)
                                  : (g_qbf + (size_t)by * 128 * Dsz);
    // mask: real mask for q0 tiles; synthetic validity mask for masked tiles
    if (tid < 128) maskSh[tid] = isB ? ((jb + tid < count) ? 1.f : 0.f)
                                     : maskp[by * 128 + tid];

    uint32_t sbase = (uint32_t)__cvta_generic_to_shared(buf);

    // cp.async: row r=(tid>>3)+64t, chunk c=tid&7; swizzle chunk' = c ^ (r&7)
    const uint32_t off0 =
        (uint32_t)(((tid >> 3) << 7) + ((((tid & 7) ^ ((tid >> 3) & 7))) << 4)); // +8192*t
    const uint32_t gof0 = (uint32_t)((tid >> 3) * 1024 + (tid & 7) * 16);        // +65536*t

    float acc[2][4][4];
    #pragma unroll
    for (int mt = 0; mt < 2; ++mt)
        #pragma unroll
        for (int nt = 0; nt < 4; ++nt)
            #pragma unroll
            for (int j = 0; j < 4; ++j) acc[mt][nt][j] = 0.f;

    auto issue = [&](int ks, int s) {
        uint32_t ab = sbase + s * STG + off0;
        uint32_t bb = ab + ASZ;
        const char* gA = (const char*)gp + ks * 128 + gof0;
        const char* gB = (const char*)gq + ks * 128 + gof0;
        #pragma unroll
        for (int t = 0; t < 2; ++t) {
            asm volatile("cp.async.cg.shared.global [%0],[%1],16;"
                         :: "r"(ab + t * 8192u), "l"(gA + t * 65536));
            asm volatile("cp.async.cg.shared.global [%0],[%1],16;"
                         :: "r"(bb + t * 8192u), "l"(gB + t * 65536));
        }
        asm volatile("cp.async.commit_group;");
    };

    const int rA  = wm * 32 + (lane & 15);
    const uint32_t a7  = (uint32_t)(rA & 7);
    const uint32_t aRowOff = (uint32_t)(rA << 7);
    const int cA0 = lane >> 4;
    const int bq  = lane >> 3;
    const int rB  = wn * 32 + ((bq >> 1) << 3) + (lane & 7);
    const uint32_t b7  = (uint32_t)(lane & 7);
    const uint32_t bRowOff = (uint32_t)(rB << 7);
    const int cB0 = bq & 1;

    auto compute = [&](int s) {
        uint32_t ab = sbase + s * STG + aRowOff;
        uint32_t bb = sbase + s * STG + ASZ + bRowOff;
        #pragma unroll
        for (int kk = 0; kk < 4; ++kk) {
            uint32_t cA = (uint32_t)(cA0 + 2 * kk) ^ a7;
            uint32_t cB = (uint32_t)(cB0 + 2 * kk) ^ b7;
            uint32_t A[2][4];
            #pragma unroll
            for (int mt = 0; mt < 2; ++mt) {
                uint32_t ad = ab + mt * 2048u + (cA << 4);
                asm volatile("ldmatrix.sync.aligned.m8n8.x4.shared.b16 {%0,%1,%2,%3},[%4];"
                             : "=r"(A[mt][0]), "=r"(A[mt][1]), "=r"(A[mt][2]), "=r"(A[mt][3])
                             : "r"(ad));
            }
            #pragma unroll
            for (int np = 0; np < 2; ++np) {
                uint32_t bd = bb + np * 2048u + (cB << 4);
                uint32_t B0, B1, B2, B3;
                asm volatile("ldmatrix.sync.aligned.m8n8.x4.shared.b16 {%0,%1,%2,%3},[%4];"
                             : "=r"(B0), "=r"(B1), "=r"(B2), "=r"(B3) : "r"(bd));
                #pragma unroll
                for (int mt = 0; mt < 2; ++mt) {
                    MMA16816(acc[mt][2 * np],     A[mt], B0, B1);
                    MMA16816(acc[mt][2 * np + 1], A[mt], B2, B3);
                }
            }
        }
    };

    // 3-stage pipeline, one barrier per K-step
    issue(0, 0);
    issue(1, 1);
    #pragma unroll 1
    for (int ks = 0; ks < 8; ++ks) {
        int s = ks % 3;
        if (ks < 7) asm volatile("cp.async.wait_group 1;");
        else        asm volatile("cp.async.wait_group 0;");
        __syncthreads();
        compute(s);
        if (ks < 6) issue(ks + 2, (ks + 2) % 3);
    }
    __syncthreads();   // all compute done before smem reuse

    // ============== register-level sumexp ==============
    // lane owns rows r0=wm*32+(lane>>2) + {0,8,16,24}, cols wn*32+nt*8+2*(lane&3)+{0,1}
    float sAllR[4] = {0.f, 0.f, 0.f, 0.f};
    float sMskR[4] = {0.f, 0.f, 0.f, 0.f};
    {
        int cb = wn * 32 + 2 * (lane & 3);
        #pragma unroll
        for (int nt = 0; nt < 4; ++nt) {
            float m0 = maskSh[cb + nt * 8];
            float m1 = maskSh[cb + nt * 8 + 1];
            #pragma unroll
            for (int mt = 0; mt < 2; ++mt) {
                float e0 = ex2f(K2f * acc[mt][nt][0]);
                float e1 = ex2f(K2f * acc[mt][nt][1]);
                float e2 = ex2f(K2f * acc[mt][nt][2]);
                float e3 = ex2f(K2f * acc[mt][nt][3]);
                sAllR[2 * mt]     += e0 + e1;
                sAllR[2 * mt + 1] += e2 + e3;
                sMskR[2 * mt]     += (m0 != 0.f ? e0 : 0.f) + (m1 != 0.f ? e1 : 0.f);
                sMskR[2 * mt + 1] += (m0 != 0.f ? e2 : 0.f) + (m1 != 0.f ? e3 : 0.f);
            }
        }
        #pragma unroll
        for (int o = 1; o < 4; o <<= 1) {
            #pragma unroll
            for (int i = 0; i < 4; ++i) {
                sAllR[i] += __shfl_xor_sync(0xffffffffu, sAllR[i], o);
                sMskR[i] += __shfl_xor_sync(0xffffffffu, sMskR[i], o);
            }
        }
    }
    // rows per index: {0:+0, 1:+8, 2:+16, 3:+24} relative to wm*32+(lane>>2)
    float* sAllSh = (float*)(buf + 69632);            // 128 x 4 floats
    float* sMskSh = sAllSh + 512;                     // 128 x 4 floats
    if ((lane & 3) == 0) {
        int rr = wm * 32 + (lane >> 2);
        #pragma unroll
        for (int i = 0; i < 4; ++i) {
            sAllSh[(rr + i * 8) * 4 + wn] = sAllR[i];
            sMskSh[(rr + i * 8) * 4 + wn] = sMskR[i];
        }
    }

    // ---- C tile -> smem for top-10 only (68096 B, disjoint from rowsums) ----
    float* Csh = (float*)buf;
    #pragma unroll
    for (int mt = 0; mt < 2; ++mt)
        #pragma unroll
        for (int nt = 0; nt < 4; ++nt) {
            int r = wm * 32 + mt * 16 + (lane >> 2);
            int c = wn * 32 + nt * 8 + 2 * (lane & 3);
            Csh[r * CPAD + c]           = acc[mt][nt][0];
            Csh[r * CPAD + c + 1]       = acc[mt][nt][1];
            Csh[(r + 8) * CPAD + c]     = acc[mt][nt][2];
            Csh[(r + 8) * CPAD + c + 1] = acc[mt][nt][3];
        }
    __syncthreads();

    // ---- combine row sums, store ----
    if (tid < 128) {
        int gb = bx * 128 + tid;
        float sa = sAllSh[tid * 4] + sAllSh[tid * 4 + 1] +
                   sAllSh[tid * 4 + 2] + sAllSh[tid * 4 + 3];
        float sm = sMskSh[tid * 4] + sMskSh[tid * 4 + 1] +
                   sMskSh[tid * 4 + 2] + sMskSh[tid * 4 + 3];
        if (!isB) {
            size_t si = (size_t)by * Bsz + gb;
            g_s1[si]  = sa;
            g_s1m[si] = sm;
        } else {
            g_s2b[(size_t)(by - NT2) * Bsz + gb] = sm;
        }
    }

    // ---- top-10: negative rows only ----
    if (tid < 256) {
        int  r     = tid & 127;
        bool roleB = (tid >= 128);
        int  gb    = bx * 128 + r;
        if (label[gb] == -1) {
            float top[10];
            #pragma unroll
            for (int i = 0; i < 10; ++i) top[i] = -FLT_MAX;
            const float* Crow = Csh + r * CPAD;
            if (!isB) {
                if (!roleB) {
                    for (int c = 0; c < 128; ++c) ins10(top, Crow[c]);
                    size_t ti = ((size_t)by * 256 + (gb >> 2)) * 10;
                    #pragma unroll
                    for (int i = 0; i < 10; ++i) g_t1[ti + i] = top[i];
                } else {
                    for (int c = 0; c < 128; ++c)
                        if (maskSh[c] == 0.f) ins10(top, Crow[c]);
                    size_t ti = ((size_t)by * 256 + (gb >> 2)) * 10;
                    #pragma unroll
                    for (int i = 0; i < 10; ++i) g_t1u[ti + i] = top[i];
                }
            } else if (!roleB) {
                int nvalid = count - jb; if (nvalid > 128) nvalid = 128;
                for (int c = 0; c < nvalid; ++c) ins10(top, Crow[c]);
                size_t ti = ((size_t)(by - NT2) * 256 + (gb >> 2)) * 10;
                #pragma unroll
                for (int i = 0; i < 10; ++i) g_t2b[ti + i] = top[i];
            }
        }
    }
}

// =====================================================================
// Pass 2: per-row merge
// =====================================================================
__global__ void __launch_bounds__(256) k_pass2(const float* __restrict__ p,
                                               const float* __restrict__ q,
                                               const float* __restrict__ maskp,
                                               const int* __restrict__ label) {
    __shared__ float red[256];
    __shared__ float red2[256];
    __shared__ float red3[256];
    __shared__ float cand[2560];
    __shared__ float wv_[8];
    __shared__ int   wi_[8];

    int b = blockIdx.x, tid = threadIdx.x;
    int lab = label[b];

    if (lab != -1) {
        float s1 = 0.f, s1m = 0.f, s2b = 0.f;
        for (int t = tid; t < NT2; t += 256) {
            s1  += g_s1 [(size_t)t * Bsz + b];
            s1m += g_s1m[(size_t)t * Bsz + b];
            if (t < MT2) s2b += g_s2b[(size_t)t * Bsz + b];
        }
        red[tid] = s1; red2[tid] = s1m; red3[tid] = s2b;
        __syncthreads();
        for (int o = 128; o > 0; o >>= 1) {
            if (tid < o) {
                red[tid]  += red[tid + o];
                red2[tid] += red2[tid + o];
                red3[tid] += red3[tid + o];
            }
            __syncthreads();
        }
        float S1 = red[0];
        float S2 = red[0] - red2[0] + red3[0];
        __syncthreads();

        float d1 = 0.f, d2 = 0.f;
        float mk = maskp[lab];
        const float* pr = p + (size_t)b * Dsz;
        const float* q0 = q + (size_t)lab * Dsz;
        const float* q1 = q0 + (size_t)Qsz * Dsz;
        for (int d = tid; d < Dsz; d += 256) {
            float pv = pr[d], a0 = q0[d], a1 = q1[d];
            float wv = mk * a1 + (1.f - mk) * a0;
            d1 += pv * a0;
            d2 += pv * wv;
        }
        red[tid] = d1; red2[tid] = d2;
        __syncthreads();
        for (int o = 128; o > 0; o >>= 1) {
            if (tid < o) { red[tid] += red[tid + o]; red2[tid] += red2[tid + o]; }
            __syncthreads();
        }
        if (tid == 0) {
            float gt1 = red[0], gt2 = red2[0];
            float sp1 = S1 - ex2f(K2f * gt1) + ex2f(K2f * (gt1 - MARGINf));
            float sp2 = S2 - ex2f(K2f * gt2) + ex2f(K2f * (gt2 - MARGINf));
            float ce1 = logf(sp1) - (gt1 - MARGINf) * SCALEf;
            float ce2 = logf(sp2) - (gt2 - MARGINf) * SCALEf;
            g_row[b] = ce1 + ce2;
        }
    } else {
        float negsum = 0.f;
        size_t base = (size_t)(b >> 2) * 10;
        for (int mat = 0; mat < 2; ++mat) {
            float top[10];
            #pragma unroll
            for (int i = 0; i < 10; ++i) top[i] = -FLT_MAX;
            int nlists = (mat == 0) ? NT2 : (NT2 + MT2);
            for (int t = tid; t < nlists; t += 256) {
                const float* L;
                if (mat == 0)        L = g_t1  + (size_t)t * 2560 + base;
                else if (t < NT2)    L = g_t1u + (size_t)t * 2560 + base;
                else                 L = g_t2b + (size_t)(t - NT2) * 2560 + base;
                #pragma unroll
                for (int i = 0; i < 10; ++i) {
                    float v = L[i];
                    if (v <= top[9]) break;   // lists sorted descending
                    ins10(top, v);
                }
            }
            #pragma unroll
            for (int i = 0; i < 10; ++i) cand[tid * 10 + i] = top[i];
            __syncthreads();

            for (int it = 0; it < 10; ++it) {
                float bv = -FLT_MAX; int bi = -1;
                #pragma unroll
                for (int j = 0; j < 10; ++j) {
                    float v = cand[tid * 10 + j];
                    if (v > bv) { bv = v; bi = tid * 10 + j; }
                }
                #pragma unroll
                for (int o = 16; o > 0; o >>= 1) {
                    float ov = __shfl_down_sync(0xffffffffu, bv, o);
                    int   oi = __shfl_down_sync(0xffffffffu, bi, o);
                    if (ov > bv) { bv = ov; bi = oi; }
                }
                if ((tid & 31) == 0) { wv_[tid >> 5] = bv; wi_[tid >> 5] = bi; }
                __syncthreads();
                if (tid == 0) {
                    float mv = wv_[0]; int mi = wi_[0];
                    #pragma unroll
                    for (int k = 1; k < 8; ++k)
                        if (wv_[k] > mv) { mv = wv_[k]; mi = wi_[k]; }
                    cand[mi] = -FLT_MAX;
                    negsum += fmaxf(mv, 0.f);
                }
                __syncthreads();
            }
            __syncthreads();
        }
        if (tid == 0) g_row[b] = negsum * 0.1f;
    }
}

// =====================================================================
// Pass 3: scalar reduction
// =====================================================================
__global__ void k_final(const int* __restrict__ label, float* __restrict__ out) {
    __shared__ float sp[256], sn[256];
    __shared__ int   cp_[256], cn_[256];
    int tid = threadIdx.x;
    float ps = 0.f, ns = 0.f;
    int pc = 0, nc = 0;
    for (int b = tid; b < Bsz; b += 256) {
        if (label[b] != -1) { ps += g_row[b]; pc++; }
        else                { ns += g_row[b]; nc++; }
    }
    sp[tid] = ps; sn[tid] = ns; cp_[tid] = pc; cn_[tid] = nc;
    __syncthreads();
    for (int o = 128; o > 0; o >>= 1) {
        if (tid < o) {
            sp[tid] += sp[tid + o]; sn[tid] += sn[tid + o];
            cp_[tid] += cp_[tid + o]; cn_[tid] += cn_[tid + o];
        }
        __syncthreads();
    }
    if (tid == 0) {
        float r = 0.f;
        if (cp_[0] > 0) r += sp[0] / (float)cp_[0];
        if (cn_[0] > 0) r += sn[0] / (float)cn_[0];
        out[0] = r;
    }
}

// =====================================================================
extern "C" void kernel_launch(void* const* d_in, const int* in_sizes, int n_in,
                              void* d_out, int out_size) {
    const float* p   = (const float*)d_in[0];
    const float* q   = (const float*)d_in[1];
    const float* mk  = (const float*)d_in[2];
    const int*   lab = (const int*)d_in[3];
    float* out = (float*)d_out;

    const int SMEM1 = 512 + 3 * 32768;   // 98816 (2 CTAs/SM)
    cudaFuncSetAttribute(k_mm, cudaFuncAttributeMaxDynamicSharedMemorySize, SMEM1);

    k_convert<<<33280, 256>>>(p, q);
    k_scan<<<1, 1024>>>(mk);
    k_gather<<<MCAP, 128>>>(q);
    dim3 g1(8, NT2 + MT2);
    k_mm<<<g1, 512, SMEM1>>>(mk, lab);
    k_pass2<<<Bsz, 256>>>(p, q, mk, lab);
    k_final<<<1, 256>>>(lab, out);
}